// round 3
// baseline (speedup 1.0000x reference)
#include <cuda_runtime.h>
#include <math.h>

#define OBS 17
#define ACT 4
#define HID 64
#define LOG_2PI 1.8378770664093453f
#define TPB 96
typedef unsigned long long ull;

__device__ float g_Qinv[16];

__device__ __forceinline__ float tanh_fast(float v) {
    float r; asm("tanh.approx.f32 %0, %1;" : "=f"(r) : "f"(v)); return r;
}
// packed fp32x2 ops (Blackwell FFMA2 path — ptxas never auto-fuses these)
__device__ __forceinline__ ull fma2(ull a, ull b, ull c) {
    ull d; asm("fma.rn.f32x2 %0, %1, %2, %3;" : "=l"(d) : "l"(a), "l"(b), "l"(c)); return d;
}
__device__ __forceinline__ ull dup2(float v) {
    ull d; asm("mov.b64 %0, {%1, %1};" : "=l"(d) : "f"(v)); return d;
}
__device__ __forceinline__ ull pk2(float x, float y) {
    ull d; asm("mov.b64 %0, {%1, %2};" : "=l"(d) : "f"(x), "f"(y)); return d;
}
__device__ __forceinline__ float2 upk(ull p) {
    float2 r; asm("mov.b64 {%0, %1}, %2;" : "=f"(r.x), "=f"(r.y) : "l"(p)); return r;
}

// ---------------------------------------------------------------------------
// Prep: Qinv = (tril(L) tril(L)^T + 1e-4 I)^{-1}, once, in double.
// ---------------------------------------------------------------------------
__global__ void qinv_kernel(const float* __restrict__ L) {
    if (threadIdx.x != 0 || blockIdx.x != 0) return;
    double Lt[4][4];
    for (int i = 0; i < 4; i++)
        for (int j = 0; j < 4; j++)
            Lt[i][j] = (j <= i) ? (double)L[i * 4 + j] : 0.0;
    double M[4][8];
    for (int i = 0; i < 4; i++) {
        for (int j = 0; j < 4; j++) {
            double s = (i == j) ? 1e-4 : 0.0;
            for (int k = 0; k < 4; k++) s += Lt[i][k] * Lt[j][k];
            M[i][j] = s;
            M[i][4 + j] = (i == j) ? 1.0 : 0.0;
        }
    }
    for (int c = 0; c < 4; c++) {
        int p = c;
        for (int r = c + 1; r < 4; r++) if (fabs(M[r][c]) > fabs(M[p][c])) p = r;
        if (p != c) for (int j = 0; j < 8; j++) { double t = M[c][j]; M[c][j] = M[p][j]; M[p][j] = t; }
        double inv = 1.0 / M[c][c];
        for (int j = 0; j < 8; j++) M[c][j] *= inv;
        for (int r = 0; r < 4; r++) if (r != c) {
            double f = M[r][c];
            for (int j = 0; j < 8; j++) M[r][j] -= f * M[c][j];
        }
    }
    for (int i = 0; i < 4; i++)
        for (int j = 0; j < 4; j++)
            g_Qinv[i * 4 + j] = (float)M[i][4 + j];
}

// ---------------------------------------------------------------------------
// QP + outputs for one row
// ---------------------------------------------------------------------------
__device__ __forceinline__ void epilogue_row(
    int row, int N, bool valid,
    const float* __restrict__ grads, const float* __restrict__ f_x,
    const float* __restrict__ g_x, const float* __restrict__ sdfs,
    const float* __restrict__ action,
    const float* sQinv, const float* sMisc, const float* sLogstd, const float* sInvStd,
    float m0, float m1, float m2, float m3, float value,
    float* __restrict__ out)
{
    const int rl = valid ? row : 0;
    float G0 = 0.f, G1 = 0.f, G2 = 0.f, G3 = 0.f, gf = 0.f;
#pragma unroll
    for (int s = 0; s < OBS; s++) {
        const float gr = grads[rl * OBS + s];
        const float4 gx = *(const float4*)&g_x[rl * OBS * ACT + s * ACT];
        G0 -= gr * gx.x; G1 -= gr * gx.y; G2 -= gr * gx.z; G3 -= gr * gx.w;
        gf += gr * f_x[rl * OBS + s];
    }
    const float4 av = *(const float4*)&action[rl * ACT];
    const float h = sMisc[1] + sdfs[rl] + gf
                  - (G0 * av.x + G1 * av.y + G2 * av.z + G3 * av.w);
    const float v0 = sQinv[0]  * G0 + sQinv[1]  * G1 + sQinv[2]  * G2 + sQinv[3]  * G3;
    const float v1 = sQinv[4]  * G0 + sQinv[5]  * G1 + sQinv[6]  * G2 + sQinv[7]  * G3;
    const float v2 = sQinv[8]  * G0 + sQinv[9]  * G1 + sQinv[10] * G2 + sQinv[11] * G3;
    const float v3 = sQinv[12] * G0 + sQinv[13] * G1 + sQinv[14] * G2 + sQinv[15] * G3;
    const float denom = G0 * v0 + G1 * v1 + G2 * v2 + G3 * v3;
    const float lam = fmaxf(0.0f, -h / denom);

    float z0 = (av.x - m0) * sInvStd[0];
    float z1 = (av.y - m1) * sInvStd[1];
    float z2 = (av.z - m2) * sInvStd[2];
    float z3 = (av.w - m3) * sInvStd[3];
    float lp = -0.5f * (z0 * z0 + z1 * z1 + z2 * z2 + z3 * z3)
               - (sLogstd[0] + sLogstd[1] + sLogstd[2] + sLogstd[3])
               - 2.0f * LOG_2PI;

    if (valid) {
        *(float4*)&out[row * 4] = make_float4(m0 - lam * v0, m1 - lam * v1,
                                              m2 - lam * v2, m3 - lam * v3);
        out[4 * N + row] = lp;
        out[5 * N + row] = sMisc[2];
        out[6 * N + row] = value;
    }
}

// ---------------------------------------------------------------------------
// Main fused kernel: 2 rows per thread, packed f32x2 math.
// ---------------------------------------------------------------------------
__global__ __launch_bounds__(TPB, 3) void fused_kernel(
    const float* __restrict__ x, const float* __restrict__ sdfs,
    const float* __restrict__ grads, const float* __restrict__ f_x,
    const float* __restrict__ g_x, const float* __restrict__ action,
    const float* __restrict__ cW1, const float* __restrict__ cb1,
    const float* __restrict__ cW2, const float* __restrict__ cb2,
    const float* __restrict__ cW3, const float* __restrict__ cb3,
    const float* __restrict__ aW1, const float* __restrict__ ab1,
    const float* __restrict__ aW2, const float* __restrict__ ab2,
    const float* __restrict__ aW3, const float* __restrict__ ab3,
    const float* __restrict__ logstd, const float* __restrict__ s0,
    float* __restrict__ out, int N)
{
    __shared__ __align__(16) float sAW1[OBS * HID];
    __shared__ __align__(16) float sAW2[HID * HID];
    __shared__ __align__(16) float sAW3[HID * ACT];
    __shared__ __align__(16) float sCW1[OBS * HID];
    __shared__ __align__(16) float sCW2[HID * HID];
    __shared__ __align__(16) float sCW3[HID];
    __shared__ __align__(16) float sAb1[HID], sAb2[HID], sCb1[HID], sCb2[HID];
    __shared__ __align__(16) float sAb3[ACT], sLogstd[ACT], sInvStd[ACT];
    __shared__ __align__(16) float sQinv[16];
    __shared__ __align__(16) float sMisc[4]; // 0: cb3, 1: s0, 2: entropy

    const int tid = threadIdx.x;
    for (int i = tid; i < OBS * HID; i += TPB) { sAW1[i] = aW1[i]; sCW1[i] = cW1[i]; }
    for (int i = tid; i < HID * HID; i += TPB) { sAW2[i] = aW2[i]; sCW2[i] = cW2[i]; }
    for (int i = tid; i < HID * ACT; i += TPB) sAW3[i] = aW3[i];
    if (tid < HID) {
        sAb1[tid] = ab1[tid]; sAb2[tid] = ab2[tid];
        sCb1[tid] = cb1[tid]; sCb2[tid] = cb2[tid];
        sCW3[tid] = cW3[tid];
    }
    if (tid < ACT) {
        float ls = logstd[tid];
        sAb3[tid] = ab3[tid];
        sLogstd[tid] = ls;
        sInvStd[tid] = expf(-ls);
    }
    if (tid < 16) sQinv[tid] = g_Qinv[tid];
    if (tid == 0) {
        sMisc[0] = cb3[0];
        sMisc[1] = s0[0];
        float e = 0.0f;
        for (int a = 0; a < ACT; a++) e += 0.5f + 0.5f * LOG_2PI + logstd[a];
        sMisc[2] = e;
    }
    __syncthreads();

    const int r0 = blockIdx.x * (2 * TPB) + tid;
    const int r1 = r0 + TPB;
    const bool ok0 = r0 < N, ok1 = r1 < N;
    const int rl0 = ok0 ? r0 : 0;
    const int rl1 = ok1 ? r1 : 0;

    // ---- observations for both rows ----
    float xA[OBS], xB[OBS];
#pragma unroll
    for (int i = 0; i < OBS; i++) { xA[i] = x[rl0 * OBS + i]; xB[i] = x[rl1 * OBS + i]; }

    float h1A[HID], h1B[HID];
    float mA0, mA1, mA2, mA3, mB0, mB1, mB2, mB3, valA, valB;

    // =============== ACTOR + CRITIC (same structure, net = 0/1) ===============
#pragma unroll 1
    for (int net = 0; net < 2; net++) {
        const float* W1 = net ? sCW1 : sAW1;
        const float* W2 = net ? sCW2 : sAW2;
        const float* B1 = net ? sCb1 : sAb1;
        const float* B2 = net ? sCb2 : sAb2;

        // ---- layer 1: 32 packed accumulators per row ----
        {
            ull hA[32], hB[32];
            const ulonglong2* bp = (const ulonglong2*)B1;
#pragma unroll
            for (int q = 0; q < 16; q++) {
                ulonglong2 bb = bp[q];
                hA[2*q] = bb.x; hA[2*q+1] = bb.y;
                hB[2*q] = bb.x; hB[2*q+1] = bb.y;
            }
#pragma unroll 1
            for (int i = 0; i < OBS; i++) {
                const ull vA = dup2(xA[i]), vB = dup2(xB[i]);
                const ulonglong2* wp = (const ulonglong2*)&W1[i * HID];
#pragma unroll
                for (int q = 0; q < 16; q++) {
                    ulonglong2 ww = wp[q];
                    hA[2*q]   = fma2(ww.x, vA, hA[2*q]);
                    hA[2*q+1] = fma2(ww.y, vA, hA[2*q+1]);
                    hB[2*q]   = fma2(ww.x, vB, hB[2*q]);
                    hB[2*q+1] = fma2(ww.y, vB, hB[2*q+1]);
                }
            }
#pragma unroll
            for (int p = 0; p < 32; p++) {
                float2 t = upk(hA[p]);
                h1A[2*p] = tanh_fast(t.x); h1A[2*p+1] = tanh_fast(t.y);
                t = upk(hB[p]);
                h1B[2*p] = tanh_fast(t.x); h1B[2*p+1] = tanh_fast(t.y);
            }
        }

        // ---- layer 2 (chunks of 16 outputs) + fused layer 3 ----
        ull mA01, mA23, mB01, mB23;   // actor mean pairs
        ull vpA, vpB;                 // critic value pairs
        if (net == 0) {
            mA01 = pk2(sAb3[0], sAb3[1]); mA23 = pk2(sAb3[2], sAb3[3]);
            mB01 = mA01; mB23 = mA23;
        } else {
            vpA = pk2(sMisc[0], 0.0f); vpB = vpA;
        }
#pragma unroll 1
        for (int c = 0; c < 4; c++) {
            ull aA[8], aB[8];
            const ulonglong2* bp = (const ulonglong2*)&B2[c * 16];
#pragma unroll
            for (int q = 0; q < 4; q++) {
                ulonglong2 bb = bp[q];
                aA[2*q] = bb.x; aA[2*q+1] = bb.y;
                aB[2*q] = bb.x; aB[2*q+1] = bb.y;
            }
#pragma unroll 8
            for (int i = 0; i < HID; i++) {
                const ull hAp = dup2(h1A[i]), hBp = dup2(h1B[i]);
                const ulonglong2* wp = (const ulonglong2*)&W2[i * HID + c * 16];
#pragma unroll
                for (int q = 0; q < 4; q++) {
                    ulonglong2 ww = wp[q];
                    aA[2*q]   = fma2(ww.x, hAp, aA[2*q]);
                    aA[2*q+1] = fma2(ww.y, hAp, aA[2*q+1]);
                    aB[2*q]   = fma2(ww.x, hBp, aB[2*q]);
                    aB[2*q+1] = fma2(ww.y, hBp, aB[2*q+1]);
                }
            }
#pragma unroll
            for (int p = 0; p < 8; p++) {
                const int j = c * 16 + 2 * p;
                float2 tA = upk(aA[p]);
                tA.x = tanh_fast(tA.x); tA.y = tanh_fast(tA.y);
                float2 tB = upk(aB[p]);
                tB.x = tanh_fast(tB.x); tB.y = tanh_fast(tB.y);
                if (net == 0) {
                    const ulonglong2 w0 = *(const ulonglong2*)&sAW3[j * ACT];
                    const ulonglong2 w1 = *(const ulonglong2*)&sAW3[(j + 1) * ACT];
                    ull d;
                    d = dup2(tA.x); mA01 = fma2(w0.x, d, mA01); mA23 = fma2(w0.y, d, mA23);
                    d = dup2(tA.y); mA01 = fma2(w1.x, d, mA01); mA23 = fma2(w1.y, d, mA23);
                    d = dup2(tB.x); mB01 = fma2(w0.x, d, mB01); mB23 = fma2(w0.y, d, mB23);
                    d = dup2(tB.y); mB01 = fma2(w1.x, d, mB01); mB23 = fma2(w1.y, d, mB23);
                } else {
                    const ull wv = *(const ull*)&sCW3[j];
                    vpA = fma2(wv, pk2(tA.x, tA.y), vpA);
                    vpB = fma2(wv, pk2(tB.x, tB.y), vpB);
                }
            }
        }
        if (net == 0) {
            float2 a = upk(mA01), b = upk(mA23);
            mA0 = a.x; mA1 = a.y; mA2 = b.x; mA3 = b.y;
            a = upk(mB01); b = upk(mB23);
            mB0 = a.x; mB1 = a.y; mB2 = b.x; mB3 = b.y;
        } else {
            float2 a = upk(vpA); valA = a.x + a.y;
            a = upk(vpB); valB = a.x + a.y;
        }
    }

    // =============== QP + outputs, both rows ===============
    epilogue_row(r0, N, ok0, grads, f_x, g_x, sdfs, action,
                 sQinv, sMisc, sLogstd, sInvStd, mA0, mA1, mA2, mA3, valA, out);
    epilogue_row(r1, N, ok1, grads, f_x, g_x, sdfs, action,
                 sQinv, sMisc, sLogstd, sInvStd, mB0, mB1, mB2, mB3, valB, out);
}

extern "C" void kernel_launch(void* const* d_in, const int* in_sizes, int n_in,
                              void* d_out, int out_size) {
    const float* x      = (const float*)d_in[0];
    const float* sdfs   = (const float*)d_in[1];
    const float* grads  = (const float*)d_in[2];
    const float* f_x    = (const float*)d_in[3];
    const float* g_x    = (const float*)d_in[4];
    const float* action = (const float*)d_in[5];
    const float* cW1 = (const float*)d_in[6];
    const float* cb1 = (const float*)d_in[7];
    const float* cW2 = (const float*)d_in[8];
    const float* cb2 = (const float*)d_in[9];
    const float* cW3 = (const float*)d_in[10];
    const float* cb3 = (const float*)d_in[11];
    const float* aW1 = (const float*)d_in[12];
    const float* ab1 = (const float*)d_in[13];
    const float* aW2 = (const float*)d_in[14];
    const float* ab2 = (const float*)d_in[15];
    const float* aW3 = (const float*)d_in[16];
    const float* ab3 = (const float*)d_in[17];
    const float* logstd = (const float*)d_in[18];
    const float* L      = (const float*)d_in[19];
    const float* s0     = (const float*)d_in[20];

    const int N = in_sizes[0] / OBS;
    float* out = (float*)d_out;

    qinv_kernel<<<1, 32>>>(L);
    const int rowsPerBlock = 2 * TPB;
    const int blocks = (N + rowsPerBlock - 1) / rowsPerBlock;
    fused_kernel<<<blocks, TPB>>>(x, sdfs, grads, f_x, g_x, action,
                                  cW1, cb1, cW2, cb2, cW3, cb3,
                                  aW1, ab1, aW2, ab2, aW3, ab3,
                                  logstd, s0, out, N);
}

// round 4
// speedup vs baseline: 1.5115x; 1.5115x over previous
#include <cuda_runtime.h>
#include <math.h>

#define OBS 17
#define ACT 4
#define HID 64
#define LOG_2PI 1.8378770664093453f
#define TPB 128
typedef unsigned long long ull;

__device__ float g_Qinv[16];

__device__ __forceinline__ float tanh_fast(float v) {
    float r; asm("tanh.approx.f32 %0, %1;" : "=f"(r) : "f"(v)); return r;
}
__device__ __forceinline__ ull fma2(ull a, ull b, ull c) {
    ull d; asm("fma.rn.f32x2 %0, %1, %2, %3;" : "=l"(d) : "l"(a), "l"(b), "l"(c)); return d;
}
__device__ __forceinline__ ull dup2(float v) {
    ull d; asm("mov.b64 %0, {%1, %1};" : "=l"(d) : "f"(v)); return d;
}
__device__ __forceinline__ ull pk2(float x, float y) {
    ull d; asm("mov.b64 %0, {%1, %2};" : "=l"(d) : "f"(x), "f"(y)); return d;
}
__device__ __forceinline__ float2 upk(ull p) {
    float2 r; asm("mov.b64 {%0, %1}, %2;" : "=f"(r.x), "=f"(r.y) : "l"(p)); return r;
}

// ---------------------------------------------------------------------------
// Prep: Qinv = (tril(L) tril(L)^T + 1e-4 I)^{-1}, once, in double.
// ---------------------------------------------------------------------------
__global__ void qinv_kernel(const float* __restrict__ L) {
    if (threadIdx.x != 0 || blockIdx.x != 0) return;
    double Lt[4][4];
    for (int i = 0; i < 4; i++)
        for (int j = 0; j < 4; j++)
            Lt[i][j] = (j <= i) ? (double)L[i * 4 + j] : 0.0;
    double M[4][8];
    for (int i = 0; i < 4; i++) {
        for (int j = 0; j < 4; j++) {
            double s = (i == j) ? 1e-4 : 0.0;
            for (int k = 0; k < 4; k++) s += Lt[i][k] * Lt[j][k];
            M[i][j] = s;
            M[i][4 + j] = (i == j) ? 1.0 : 0.0;
        }
    }
    for (int c = 0; c < 4; c++) {
        int p = c;
        for (int r = c + 1; r < 4; r++) if (fabs(M[r][c]) > fabs(M[p][c])) p = r;
        if (p != c) for (int j = 0; j < 8; j++) { double t = M[c][j]; M[c][j] = M[p][j]; M[p][j] = t; }
        double inv = 1.0 / M[c][c];
        for (int j = 0; j < 8; j++) M[c][j] *= inv;
        for (int r = 0; r < 4; r++) if (r != c) {
            double f = M[r][c];
            for (int j = 0; j < 8; j++) M[r][j] -= f * M[c][j];
        }
    }
    for (int i = 0; i < 4; i++)
        for (int j = 0; j < 4; j++)
            g_Qinv[i * 4 + j] = (float)M[i][4 + j];
}

// ---------------------------------------------------------------------------
// QP + outputs for one row
// ---------------------------------------------------------------------------
__device__ __forceinline__ void epilogue_row(
    int row, int N, bool valid,
    const float* __restrict__ grads, const float* __restrict__ f_x,
    const float* __restrict__ g_x, const float* __restrict__ sdfs,
    const float* __restrict__ action,
    const float* sQinv, const float* sMisc, const float* sLogstd, const float* sInvStd,
    float m0, float m1, float m2, float m3, float value,
    float* __restrict__ out)
{
    const int rl = valid ? row : 0;
    float G0 = 0.f, G1 = 0.f, G2 = 0.f, G3 = 0.f, gf = 0.f;
#pragma unroll
    for (int s = 0; s < OBS; s++) {
        const float gr = grads[rl * OBS + s];
        const float4 gx = *(const float4*)&g_x[rl * OBS * ACT + s * ACT];
        G0 -= gr * gx.x; G1 -= gr * gx.y; G2 -= gr * gx.z; G3 -= gr * gx.w;
        gf += gr * f_x[rl * OBS + s];
    }
    const float4 av = *(const float4*)&action[rl * ACT];
    const float h = sMisc[1] + sdfs[rl] + gf
                  - (G0 * av.x + G1 * av.y + G2 * av.z + G3 * av.w);
    const float v0 = sQinv[0]  * G0 + sQinv[1]  * G1 + sQinv[2]  * G2 + sQinv[3]  * G3;
    const float v1 = sQinv[4]  * G0 + sQinv[5]  * G1 + sQinv[6]  * G2 + sQinv[7]  * G3;
    const float v2 = sQinv[8]  * G0 + sQinv[9]  * G1 + sQinv[10] * G2 + sQinv[11] * G3;
    const float v3 = sQinv[12] * G0 + sQinv[13] * G1 + sQinv[14] * G2 + sQinv[15] * G3;
    const float denom = G0 * v0 + G1 * v1 + G2 * v2 + G3 * v3;
    const float lam = fmaxf(0.0f, -h / denom);

    float z0 = (av.x - m0) * sInvStd[0];
    float z1 = (av.y - m1) * sInvStd[1];
    float z2 = (av.z - m2) * sInvStd[2];
    float z3 = (av.w - m3) * sInvStd[3];
    float lp = -0.5f * (z0 * z0 + z1 * z1 + z2 * z2 + z3 * z3)
               - (sLogstd[0] + sLogstd[1] + sLogstd[2] + sLogstd[3])
               - 2.0f * LOG_2PI;

    if (valid) {
        *(float4*)&out[row * 4] = make_float4(m0 - lam * v0, m1 - lam * v1,
                                              m2 - lam * v2, m3 - lam * v3);
        out[4 * N + row] = lp;
        out[5 * N + row] = sMisc[2];
        out[6 * N + row] = value;
    }
}

// ---------------------------------------------------------------------------
// Main fused kernel: 2 rows/thread, packed f32x2 math, chunked layers.
// ---------------------------------------------------------------------------
__global__ __launch_bounds__(TPB, 2) void fused_kernel(
    const float* __restrict__ x, const float* __restrict__ sdfs,
    const float* __restrict__ grads, const float* __restrict__ f_x,
    const float* __restrict__ g_x, const float* __restrict__ action,
    const float* __restrict__ cW1, const float* __restrict__ cb1,
    const float* __restrict__ cW2, const float* __restrict__ cb2,
    const float* __restrict__ cW3, const float* __restrict__ cb3,
    const float* __restrict__ aW1, const float* __restrict__ ab1,
    const float* __restrict__ aW2, const float* __restrict__ ab2,
    const float* __restrict__ aW3, const float* __restrict__ ab3,
    const float* __restrict__ logstd, const float* __restrict__ s0,
    float* __restrict__ out, int N)
{
    __shared__ __align__(16) float sAW1[OBS * HID];
    __shared__ __align__(16) float sAW2[HID * HID];
    __shared__ __align__(16) float sAW3[HID * ACT];
    __shared__ __align__(16) float sCW1[OBS * HID];
    __shared__ __align__(16) float sCW2[HID * HID];
    __shared__ __align__(16) float sCW3[HID];
    __shared__ __align__(16) float sAb1[HID], sAb2[HID], sCb1[HID], sCb2[HID];
    __shared__ __align__(16) float sAb3[ACT], sLogstd[ACT], sInvStd[ACT];
    __shared__ __align__(16) float sQinv[16];
    __shared__ __align__(16) float sMisc[4]; // 0: cb3, 1: s0, 2: entropy

    const int tid = threadIdx.x;
    for (int i = tid; i < OBS * HID; i += TPB) { sAW1[i] = aW1[i]; sCW1[i] = cW1[i]; }
    for (int i = tid; i < HID * HID; i += TPB) { sAW2[i] = aW2[i]; sCW2[i] = cW2[i]; }
    for (int i = tid; i < HID * ACT; i += TPB) sAW3[i] = aW3[i];
    if (tid < HID) {
        sAb1[tid] = ab1[tid]; sAb2[tid] = ab2[tid];
        sCb1[tid] = cb1[tid]; sCb2[tid] = cb2[tid];
        sCW3[tid] = cW3[tid];
    }
    if (tid < ACT) {
        float ls = logstd[tid];
        sAb3[tid] = ab3[tid];
        sLogstd[tid] = ls;
        sInvStd[tid] = expf(-ls);
    }
    if (tid < 16) sQinv[tid] = g_Qinv[tid];
    if (tid == 0) {
        sMisc[0] = cb3[0];
        sMisc[1] = s0[0];
        float e = 0.0f;
        for (int a = 0; a < ACT; a++) e += 0.5f + 0.5f * LOG_2PI + logstd[a];
        sMisc[2] = e;
    }
    __syncthreads();

    const int r0 = blockIdx.x * (2 * TPB) + tid;
    const int r1 = r0 + TPB;
    const bool ok0 = r0 < N, ok1 = r1 < N;
    const int rl0 = ok0 ? r0 : 0;
    const int rl1 = ok1 ? r1 : 0;

    // ---- observations for both rows (live across both nets; cap=256 has room) ----
    float xA[OBS], xB[OBS];
#pragma unroll
    for (int i = 0; i < OBS; i++) { xA[i] = x[rl0 * OBS + i]; xB[i] = x[rl1 * OBS + i]; }

    float h1A[HID], h1B[HID];   // scalar floats: no 64-bit alignment pressure
    float mA0, mA1, mA2, mA3, mB0, mB1, mB2, mB3, valA, valB;

    // =============== ACTOR + CRITIC (net = 0/1) ===============
#pragma unroll 1
    for (int net = 0; net < 2; net++) {
        const float* W1 = net ? sCW1 : sAW1;
        const float* W2 = net ? sCW2 : sAW2;
        const float* B1 = net ? sCb1 : sAb1;
        const float* B2 = net ? sCb2 : sAb2;

        // ---- layer 1: two chunks of 32 outputs (16 ull accum per row per chunk) ----
#pragma unroll 1
        for (int c1 = 0; c1 < 2; c1++) {
            ull hA[16], hB[16];
            const ulonglong2* bp = (const ulonglong2*)&B1[c1 * 32];
#pragma unroll
            for (int q = 0; q < 8; q++) {
                ulonglong2 bb = bp[q];
                hA[2*q] = bb.x; hA[2*q+1] = bb.y;
                hB[2*q] = bb.x; hB[2*q+1] = bb.y;
            }
#pragma unroll 1
            for (int i = 0; i < OBS; i++) {
                const ull vA = dup2(xA[i]), vB = dup2(xB[i]);
                const ulonglong2* wp = (const ulonglong2*)&W1[i * HID + c1 * 32];
#pragma unroll
                for (int q = 0; q < 8; q++) {
                    ulonglong2 ww = wp[q];
                    hA[2*q]   = fma2(ww.x, vA, hA[2*q]);
                    hA[2*q+1] = fma2(ww.y, vA, hA[2*q+1]);
                    hB[2*q]   = fma2(ww.x, vB, hB[2*q]);
                    hB[2*q+1] = fma2(ww.y, vB, hB[2*q+1]);
                }
            }
#pragma unroll
            for (int p = 0; p < 16; p++) {
                float2 t = upk(hA[p]);
                h1A[c1 * 32 + 2*p]     = tanh_fast(t.x);
                h1A[c1 * 32 + 2*p + 1] = tanh_fast(t.y);
                t = upk(hB[p]);
                h1B[c1 * 32 + 2*p]     = tanh_fast(t.x);
                h1B[c1 * 32 + 2*p + 1] = tanh_fast(t.y);
            }
        }

        // ---- layer 2 (4 chunks of 16 outputs) + fused layer 3 ----
        ull mA01, mA23, mB01, mB23;   // actor mean pairs
        ull vpA, vpB;                 // critic value pairs
        if (net == 0) {
            mA01 = pk2(sAb3[0], sAb3[1]); mA23 = pk2(sAb3[2], sAb3[3]);
            mB01 = mA01; mB23 = mA23;
        } else {
            vpA = pk2(sMisc[0], 0.0f); vpB = vpA;
        }
#pragma unroll 1
        for (int c = 0; c < 4; c++) {
            ull aA[8], aB[8];
            const ulonglong2* bp = (const ulonglong2*)&B2[c * 16];
#pragma unroll
            for (int q = 0; q < 4; q++) {
                ulonglong2 bb = bp[q];
                aA[2*q] = bb.x; aA[2*q+1] = bb.y;
                aB[2*q] = bb.x; aB[2*q+1] = bb.y;
            }
#pragma unroll 8
            for (int i = 0; i < HID; i++) {
                const ull hAp = dup2(h1A[i]), hBp = dup2(h1B[i]);
                const ulonglong2* wp = (const ulonglong2*)&W2[i * HID + c * 16];
#pragma unroll
                for (int q = 0; q < 4; q++) {
                    ulonglong2 ww = wp[q];
                    aA[2*q]   = fma2(ww.x, hAp, aA[2*q]);
                    aA[2*q+1] = fma2(ww.y, hAp, aA[2*q+1]);
                    aB[2*q]   = fma2(ww.x, hBp, aB[2*q]);
                    aB[2*q+1] = fma2(ww.y, hBp, aB[2*q+1]);
                }
            }
#pragma unroll
            for (int p = 0; p < 8; p++) {
                const int j = c * 16 + 2 * p;
                float2 tA = upk(aA[p]);
                tA.x = tanh_fast(tA.x); tA.y = tanh_fast(tA.y);
                float2 tB = upk(aB[p]);
                tB.x = tanh_fast(tB.x); tB.y = tanh_fast(tB.y);
                if (net == 0) {
                    const ulonglong2 w0 = *(const ulonglong2*)&sAW3[j * ACT];
                    const ulonglong2 w1 = *(const ulonglong2*)&sAW3[(j + 1) * ACT];
                    ull d;
                    d = dup2(tA.x); mA01 = fma2(w0.x, d, mA01); mA23 = fma2(w0.y, d, mA23);
                    d = dup2(tA.y); mA01 = fma2(w1.x, d, mA01); mA23 = fma2(w1.y, d, mA23);
                    d = dup2(tB.x); mB01 = fma2(w0.x, d, mB01); mB23 = fma2(w0.y, d, mB23);
                    d = dup2(tB.y); mB01 = fma2(w1.x, d, mB01); mB23 = fma2(w1.y, d, mB23);
                } else {
                    const ull wv = *(const ull*)&sCW3[j];
                    vpA = fma2(wv, pk2(tA.x, tA.y), vpA);
                    vpB = fma2(wv, pk2(tB.x, tB.y), vpB);
                }
            }
        }
        if (net == 0) {
            float2 a = upk(mA01), b = upk(mA23);
            mA0 = a.x; mA1 = a.y; mA2 = b.x; mA3 = b.y;
            a = upk(mB01); b = upk(mB23);
            mB0 = a.x; mB1 = a.y; mB2 = b.x; mB3 = b.y;
        } else {
            float2 a = upk(vpA); valA = a.x + a.y;
            a = upk(vpB); valB = a.x + a.y;
        }
    }

    // =============== QP + outputs, both rows ===============
    epilogue_row(r0, N, ok0, grads, f_x, g_x, sdfs, action,
                 sQinv, sMisc, sLogstd, sInvStd, mA0, mA1, mA2, mA3, valA, out);
    epilogue_row(r1, N, ok1, grads, f_x, g_x, sdfs, action,
                 sQinv, sMisc, sLogstd, sInvStd, mB0, mB1, mB2, mB3, valB, out);
}

extern "C" void kernel_launch(void* const* d_in, const int* in_sizes, int n_in,
                              void* d_out, int out_size) {
    const float* x      = (const float*)d_in[0];
    const float* sdfs   = (const float*)d_in[1];
    const float* grads  = (const float*)d_in[2];
    const float* f_x    = (const float*)d_in[3];
    const float* g_x    = (const float*)d_in[4];
    const float* action = (const float*)d_in[5];
    const float* cW1 = (const float*)d_in[6];
    const float* cb1 = (const float*)d_in[7];
    const float* cW2 = (const float*)d_in[8];
    const float* cb2 = (const float*)d_in[9];
    const float* cW3 = (const float*)d_in[10];
    const float* cb3 = (const float*)d_in[11];
    const float* aW1 = (const float*)d_in[12];
    const float* ab1 = (const float*)d_in[13];
    const float* aW2 = (const float*)d_in[14];
    const float* ab2 = (const float*)d_in[15];
    const float* aW3 = (const float*)d_in[16];
    const float* ab3 = (const float*)d_in[17];
    const float* logstd = (const float*)d_in[18];
    const float* L      = (const float*)d_in[19];
    const float* s0     = (const float*)d_in[20];

    const int N = in_sizes[0] / OBS;
    float* out = (float*)d_out;

    qinv_kernel<<<1, 32>>>(L);
    const int rowsPerBlock = 2 * TPB;
    const int blocks = (N + rowsPerBlock - 1) / rowsPerBlock;
    fused_kernel<<<blocks, TPB>>>(x, sdfs, grads, f_x, g_x, action,
                                  cW1, cb1, cW2, cb2, cW3, cb3,
                                  aW1, ab1, aW2, ab2, aW3, ab3,
                                  logstd, s0, out, N);
}